// round 15
// baseline (speedup 1.0000x reference)
#include <cuda_runtime.h>
#include <cuda_fp16.h>
#include <math.h>
#include <stdint.h>

// ---------------------------------------------------------------------------
// Problem constants
// ---------------------------------------------------------------------------
#define B       1024
#define D       512
#define C       100000
#define TM      128                    // CTA tile rows
#define TN      128                    // CTA tile classes
#define NT      ((C + TN - 1) / TN)    // 782 class tiles
#define NTE     (NT * 2)               // 2 col-half partials per class tile
#define NTILES  (8 * NT)               // 6256 total tiles (8 row x 782 class)
#define GRIDP   296                    // persistent CTAs (148 SM x 2)
#define KCHUNK  64                     // fp16 K elems per chunk (128B rows)
#define NCHUNK  (D / KCHUNK)           // 8 chunks per tile
#define SCALE_F 64.0f
#define L2E_64  92.33248261689366f     // 64 * log2(e)

// ArcFace margin constants (margin = 0.5)
#define COS_M  0.8775825618903728f
#define SIN_M  0.47942553860420301f
#define TH_M  (-0.8775825618903728f)
#define MM_M   0.23971276930210151f

// smem: per stage A tile 128x128B (16KB) + B tile 128x128B (16KB)
#define TILE_BYTES  16384
#define STAGE_BYTES (2 * TILE_BYTES)
#define SMEM_BYTES  (3 * STAGE_BYTES)      // 98304 -> 2 CTA/SM

// Scratch (__device__ globals; no allocations allowed).
// g_winv is padded to NT*TN; CUDA zero-initializes __device__ globals and we
// never write the pad, so OOB classes read winv == 0 -> exp term ~ e^-64.
__device__ __half g_Eh[(size_t)B * D];
__device__ __half g_Wh[(size_t)C * D];
__device__ float  g_einv[B];
__device__ float  g_winv[NT * TN];
__device__ float  g_psum[(size_t)B * NTE];
__device__ float  g_nll[B];

// ---------------------------------------------------------------------------
// PTX helpers (base ISA only -- nothing gated on sm_103a)
// ---------------------------------------------------------------------------
__device__ __forceinline__ uint32_t smem_u32(const void* p) {
    uint32_t a;
    asm("{ .reg .u64 t; cvta.to.shared.u64 t, %1; cvt.u32.u64 %0, t; }"
        : "=r"(a) : "l"(p));
    return a;
}
__device__ __forceinline__ void cp16(uint32_t dst, const void* src) {
    asm volatile("cp.async.cg.shared.global [%0], [%1], 16;"
                 :: "r"(dst), "l"(src));
}
__device__ __forceinline__ void cp_commit() {
    asm volatile("cp.async.commit_group;" ::: "memory");
}
template <int N> __device__ __forceinline__ void cp_wait() {
    asm volatile("cp.async.wait_group %0;" :: "n"(N) : "memory");
}
__device__ __forceinline__ void st_zero16(uint32_t dst) {
    asm volatile("st.shared.v4.u32 [%0], {%1, %1, %1, %1};"
                 :: "r"(dst), "r"(0u) : "memory");
}
__device__ __forceinline__ void ldsm4(uint32_t* r, uint32_t addr) {
    asm volatile("ldmatrix.sync.aligned.m8n8.x4.shared.b16 {%0,%1,%2,%3}, [%4];"
                 : "=r"(r[0]), "=r"(r[1]), "=r"(r[2]), "=r"(r[3]) : "r"(addr));
}
__device__ __forceinline__ void mma_f16(float* d, const uint32_t* a,
                                        const uint32_t* b) {
    asm volatile(
        "mma.sync.aligned.m16n8k16.row.col.f32.f16.f16.f32 "
        "{%0,%1,%2,%3}, {%4,%5,%6,%7}, {%8,%9}, {%0,%1,%2,%3};"
        : "+f"(d[0]), "+f"(d[1]), "+f"(d[2]), "+f"(d[3])
        : "r"(a[0]), "r"(a[1]), "r"(a[2]), "r"(a[3]), "r"(b[0]), "r"(b[1]));
}
__device__ __forceinline__ float ex2(float x) {
    float r;
    asm("ex2.approx.ftz.f32 %0, %1;" : "=f"(r) : "f"(x));
    return r;
}

// ---------------------------------------------------------------------------
// Norm + fp16-convert kernels (one warp per row, single fused pass)
// ---------------------------------------------------------------------------
__global__ void e_conv_kernel(const float* __restrict__ E) {
    int warp = (blockIdx.x * blockDim.x + threadIdx.x) >> 5;
    int lane = threadIdx.x & 31;
    if (warp >= B) return;
    const float* row = E + (size_t)warp * D;
    __half2* dst = (__half2*)(g_Eh + (size_t)warp * D);
    float ss = 0.f;
    #pragma unroll
    for (int j = 0; j < 4; j++) {
        float4 v = *(const float4*)(row + (j * 32 + lane) * 4);
        ss = fmaf(v.x, v.x, fmaf(v.y, v.y, fmaf(v.z, v.z, fmaf(v.w, v.w, ss))));
        dst[(j * 32 + lane) * 2]     = __floats2half2_rn(v.x, v.y);
        dst[(j * 32 + lane) * 2 + 1] = __floats2half2_rn(v.z, v.w);
    }
    #pragma unroll
    for (int o = 16; o > 0; o >>= 1) ss += __shfl_xor_sync(0xffffffffu, ss, o);
    if (lane == 0) g_einv[warp] = 1.0f / fmaxf(sqrtf(ss), 1e-12f);
}

__global__ void w_conv_kernel(const float* __restrict__ W) {
    int warp = (blockIdx.x * blockDim.x + threadIdx.x) >> 5;
    int lane = threadIdx.x & 31;
    if (warp >= C) return;
    const float* row = W + (size_t)warp * D;
    __half2* dst = (__half2*)(g_Wh + (size_t)warp * D);
    float ss = 0.f;
    #pragma unroll
    for (int j = 0; j < 4; j++) {
        float4 v = *(const float4*)(row + (j * 32 + lane) * 4);
        ss = fmaf(v.x, v.x, fmaf(v.y, v.y, fmaf(v.z, v.z, fmaf(v.w, v.w, ss))));
        dst[(j * 32 + lane) * 2]     = __floats2half2_rn(v.x, v.y);
        dst[(j * 32 + lane) * 2 + 1] = __floats2half2_rn(v.z, v.w);
    }
    #pragma unroll
    for (int o = 16; o > 0; o >>= 1) ss += __shfl_xor_sync(0xffffffffu, ss, o);
    if (lane == 0) g_winv[warp] = 1.0f / fmaxf(sqrtf(ss), 1e-12f);
}

// ---------------------------------------------------------------------------
// Main: persistent-CTA fp16 mma.sync GEMM. 296 CTAs x 256 threads; each CTA
// walks tiles bid, bid+296, ... (x-major => W-tile L2 reuse). The cp.async
// pipeline runs over one continuous chunk stream ACROSS tiles, so the next
// tile's loads overlap this tile's last MMAs and epilogue -- no per-tile
// prologue stall. One __syncthreads per chunk. Fixed-max softmax partials.
// ---------------------------------------------------------------------------
__global__ void __launch_bounds__(256, 2)
gemm_tc_kernel(void) {
    extern __shared__ char sdata[];

    const int tid  = threadIdx.x;
    const int wid  = tid >> 5;
    const int lane = tid & 31;
    const int wm   = wid >> 1;         // 0..3 : 32-row slice
    const int wn   = wid & 1;          // 0..1 : 64-col half
    const int qid  = lane >> 2;        // 0..7
    const int ql   = lane & 3;         // 0..3
    const int bid  = blockIdx.x;

    const int ntile = (NTILES - bid + GRIDP - 1) / GRIDP;   // tiles for this CTA
    const int S     = ntile * NCHUNK;                       // total chunk stream

    const uint32_t s0 = smem_u32(sdata);

    // --- issue loads for stream chunk s (A 16KB + B 16KB, XOR swizzle) ---
    auto issue_load = [&](int s) {
        if (s < S) {
            const int tile      = bid + (s >> 3) * GRIDP;
            const int k         = s & 7;
            const int rowBase   = (tile & 7) * TM;
            const int classBase = (tile >> 3) * TN;
            const uint32_t sa   = s0 + (s % 3) * STAGE_BYTES;
            const uint32_t sb   = sa + TILE_BYTES;
            const int      kof  = k * KCHUNK;
            const __half*  Ep   = g_Eh + (size_t)rowBase * D + kof;
            #pragma unroll
            for (int i = 0; i < 4; i++) {
                int idx = tid + i * 256;           // 0..1023
                int r = idx >> 3, c = idx & 7;
                uint32_t dst = sa + r * 128 + ((c ^ (r & 7)) << 4);
                cp16(dst, Ep + (size_t)r * D + c * 8);
            }
            #pragma unroll
            for (int i = 0; i < 4; i++) {
                int idx = tid + i * 256;
                int r = idx >> 3, c = idx & 7;
                int cls = classBase + r;
                uint32_t dst = sb + r * 128 + ((c ^ (r & 7)) << 4);
                if (cls < C) cp16(dst, g_Wh + (size_t)cls * D + kof + c * 8);
                else         st_zero16(dst);
            }
        }
        cp_commit();   // always commit (possibly empty) -> uniform wait counts
    };

    // ldmatrix per-lane address components
    const int aRow = (lane & 7) + ((lane >> 3) & 1) * 8;   // row within 16
    const int kgA  = lane >> 4;                            // k half
    const int bRow = (lane & 7) + (lane >> 4) * 8;         // row within 16
    const int kgB  = (lane >> 3) & 1;

    float acc[2][8][4];
    #pragma unroll
    for (int mt = 0; mt < 2; mt++)
        #pragma unroll
        for (int nt = 0; nt < 8; nt++)
            #pragma unroll
            for (int c = 0; c < 4; c++) acc[mt][nt][c] = 0.f;

    issue_load(0);
    issue_load(1);

    for (int s = 0; s < S; s++) {
        cp_wait<1>();          // chunk s landed (s+1 may still fly)
        __syncthreads();       // everyone done reading stage (s-1)%3
        issue_load(s + 2);     // targets stage (s+2)%3 == (s-1)%3

        // compute chunk s
        {
            const uint32_t sa = s0 + (s % 3) * STAGE_BYTES;
            const uint32_t sb = sa + TILE_BYTES;
            #pragma unroll
            for (int ks = 0; ks < 4; ks++) {
                uint32_t a[2][4], bb[4][4];
                const int cA = ks * 2 + kgA;
                const int cB = ks * 2 + kgB;
                const uint32_t swA = (uint32_t)((cA ^ (lane & 7)) << 4);
                const uint32_t swB = (uint32_t)((cB ^ (lane & 7)) << 4);
                #pragma unroll
                for (int mt = 0; mt < 2; mt++)
                    ldsm4(a[mt], sa + (wm * 32 + mt * 16 + aRow) * 128 + swA);
                #pragma unroll
                for (int ntp = 0; ntp < 4; ntp++)
                    ldsm4(bb[ntp], sb + (wn * 64 + ntp * 16 + bRow) * 128 + swB);
                #pragma unroll
                for (int mt = 0; mt < 2; mt++)
                    #pragma unroll
                    for (int nt = 0; nt < 8; nt++) {
                        uint32_t bfrag[2] = { bb[nt >> 1][(nt & 1) * 2],
                                              bb[nt >> 1][(nt & 1) * 2 + 1] };
                        mma_f16(acc[mt][nt], a[mt], bfrag);
                    }
            }
        }

        // --- tile boundary: epilogue (overlaps the in-flight next-tile loads)
        if ((s & 7) == 7) {
            const int tile      = bid + (s >> 3) * GRIDP;
            const int rowBase   = (tile & 7) * TM;
            const int classBase = (tile >> 3) * TN;
            const int tileIdx   = (tile >> 3) * 2 + wn;

            // winv for this warp's 64-class half (L2-hot; pad reads 0)
            float wv[16];
            #pragma unroll
            for (int nt = 0; nt < 8; nt++) {
                #pragma unroll
                for (int c = 0; c < 2; c++)
                    wv[nt * 2 + c] =
                        g_winv[classBase + wn * 64 + nt * 8 + ql * 2 + c];
            }
            #pragma unroll
            for (int mt = 0; mt < 2; mt++) {
                #pragma unroll
                for (int h = 0; h < 2; h++) {
                    const int   rloc = wm * 32 + mt * 16 + qid + h * 8;
                    const float ew   = g_einv[rowBase + rloc] * L2E_64;
                    float sum = 0.f;
                    #pragma unroll
                    for (int j = 0; j < 16; j++) {
                        float u = acc[mt][j >> 1][h * 2 + (j & 1)] * ew;
                        sum += ex2(fmaf(u, wv[j], -L2E_64));
                    }
                    sum += __shfl_xor_sync(0xffffffffu, sum, 1);
                    sum += __shfl_xor_sync(0xffffffffu, sum, 2);
                    if (ql == 0)
                        g_psum[(size_t)(rowBase + rloc) * NTE + tileIdx] = sum;
                }
            }
            // reset accumulators for the next tile
            #pragma unroll
            for (int mt = 0; mt < 2; mt++)
                #pragma unroll
                for (int nt = 0; nt < 8; nt++)
                    #pragma unroll
                    for (int c = 0; c < 4; c++) acc[mt][nt][c] = 0.f;
        }
    }
}

// ---------------------------------------------------------------------------
// Finalize stage 1: one warp per row -- sums NTE partials, computes the exact
// fp32 label dot (folded-in label_dot), applies margin correction.
// ---------------------------------------------------------------------------
__global__ void finalize_rows_kernel(const float* __restrict__ E,
                                     const float* __restrict__ W,
                                     const int* __restrict__ labels) {
    int gw   = (blockIdx.x * blockDim.x + threadIdx.x) >> 5;
    int lane = threadIdx.x & 31;
    if (gw >= B) return;

    const float* ps = g_psum + (size_t)gw * NTE;
    float s = 0.f;
    for (int t = lane; t < NTE; t += 32) s += ps[t];

    int lab = labels[gw];
    const float* e = E + (size_t)gw * D;
    const float* w = W + (size_t)lab * D;
    float dot = 0.f, ws = 0.f;
    #pragma unroll
    for (int i = 0; i < D / 32; i++) {
        float wv = w[lane + i * 32];
        dot = fmaf(e[lane + i * 32], wv, dot);
        ws  = fmaf(wv, wv, ws);
    }
    #pragma unroll
    for (int o = 16; o > 0; o >>= 1) {
        s   += __shfl_xor_sync(0xffffffffu, s, o);
        dot += __shfl_xor_sync(0xffffffffu, dot, o);
        ws  += __shfl_xor_sync(0xffffffffu, ws, o);
    }

    if (lane == 0) {
        float winv = 1.0f / fmaxf(sqrtf(ws), 1e-12f);
        float cosl = dot * g_einv[gw] * winv;
        float c2   = 1.0f - cosl * cosl;
        float sine = sqrtf(fminf(fmaxf(c2, 0.f), 1.f));
        float phi  = cosl * COS_M - sine * SIN_M;
        phi = (cosl > TH_M) ? phi : (cosl - MM_M);

        float lo = SCALE_F * cosl;   // original label logit
        float ln = SCALE_F * phi;    // margined logit
        s += expf(ln - SCALE_F) - expf(lo - SCALE_F);
        // logZ = 64 + log(s); nll = logZ - ln
        g_nll[gw] = SCALE_F + logf(s) - ln;
    }
}

__global__ void finalize_reduce_kernel(float* __restrict__ out) {
    __shared__ float red[B];
    int b = threadIdx.x;
    red[b] = g_nll[b];
    __syncthreads();
    #pragma unroll
    for (int o = B / 2; o > 0; o >>= 1) {
        if (b < o) red[b] += red[b + o];
        __syncthreads();
    }
    if (b == 0) out[0] = red[0] / (float)B;
}

// ---------------------------------------------------------------------------
extern "C" void kernel_launch(void* const* d_in, const int* in_sizes, int n_in,
                              void* d_out, int out_size) {
    const float* E      = (const float*)d_in[0];
    const float* W      = (const float*)d_in[1];
    const int*   labels = (const int*)d_in[2];
    float*       out    = (float*)d_out;

    cudaFuncSetAttribute(gemm_tc_kernel,
                         cudaFuncAttributeMaxDynamicSharedMemorySize, SMEM_BYTES);

    e_conv_kernel<<<(B * 32) / 256, 256>>>(E);
    w_conv_kernel<<<(C * 32 + 255) / 256, 256>>>(W);

    gemm_tc_kernel<<<GRIDP, 256, SMEM_BYTES>>>();

    finalize_rows_kernel<<<(B * 32 + 255) / 256, 256>>>(E, W, labels);
    finalize_reduce_kernel<<<1, B>>>(out);
}